// round 14
// baseline (speedup 1.0000x reference)
#include <cuda_runtime.h>
#include <cuda_fp16.h>
#include <math.h>
#include <stdint.h>

// Problem dims (fixed by the dataset)
#define BB   8
#define HHH  64
#define WWW  64
#define VV   4096      // HHH*WWW
#define CIN  256
#define FF   128
#define EE   256
#define COUT 256
#define SPLITK_P 8     // tmp GEMM split
#define SPLITS2  14    // stage-2 (t) split: 196 chunks / 14
#define LD2  12544     // 49*256, K of stage-2

// ---------------- scratch (static device globals; no allocation allowed) ----
__device__ __half g_phi16[BB*VV*FF];       // [b][v][f]
__device__ __half g_phiT [BB*FF*VV];       // [b][f][v]
__device__ __half g_H16  [BB*VV*EE];       // [b][v][e]
__device__ __half g_HDT  [BB*EE*VV];       // [b][e][v] = D[v]*H[v][e]
__device__ __half g_Rh   [BB*VV*CIN];      // R hi
__device__ __half g_Rl   [BB*VV*CIN];      // R lo
__device__ float  g_D    [BB*VV];
__device__ float  g_Be   [BB*EE];
__device__ float  g_a    [BB*FF];
__device__ float  g_P    [BB*FF];          // phi column sums
__device__ float  g_xpart[BB*32*CIN];
__device__ float  g_xmean[BB*CIN];
__device__ float  g_bpart[BB*16*EE];
__device__ float  g_part1[SPLITS2*BB*FF*EE];    // stage-2 partials
__device__ float  g_part2[SPLITK_P*BB*CIN*EE];  // tmp partials [zb][c][e]
__device__ __half g_xh  [BB*VV*CIN];       // [b][v][c]
__device__ __half g_xT  [BB*CIN*VV];       // [b][c][v]
__device__ __half g_xT7 [7*BB*CIN*VV];     // [dx+3][b][c][v], col-shift masked
__device__ __half g_G   [BB*FF*LD2];       // [b][f][tap*256+c]
__device__ __half g_wte [EE*LD2];          // [e][tap*256+c]
__device__ __half g_wpht[FF*CIN];          // [f][c]
__device__ __half g_at  [BB*EE*FF];        // [b][e][f] = a_f * t_fe
__device__ __half g_btmpH[BB*CIN*EE];      // hi of Binv*tmp, [b][c][e]
__device__ __half g_btmpL[BB*CIN*EE];      // lo
__device__ __half g_w2th[COUT*CIN];        // w2^T hi [o][c]
__device__ __half g_w2tl[COUT*CIN];        // w2^T lo

// ======================= PTX helpers ========================================
__device__ __forceinline__ uint32_t smem_u32(const void* p) {
    uint32_t a;
    asm("{ .reg .u64 t; cvta.to.shared.u64 t, %1; cvt.u32.u64 %0, t; }" : "=r"(a) : "l"(p));
    return a;
}
#define CP_ASYNC16(dst, src, sz) \
    asm volatile("cp.async.cg.shared.global [%0], [%1], 16, %2;" \
                 :: "r"(dst), "l"(src), "r"(sz) : "memory")
#define CP_COMMIT() asm volatile("cp.async.commit_group;" ::: "memory")
#define CP_WAIT(n)  asm volatile("cp.async.wait_group %0;" :: "n"(n) : "memory")
#define LDSM4(r, addr) \
    asm volatile("ldmatrix.sync.aligned.m8n8.x4.shared.b16 {%0,%1,%2,%3}, [%4];" \
                 : "=r"((r)[0]), "=r"((r)[1]), "=r"((r)[2]), "=r"((r)[3]) : "r"(addr))
#define MMA16816H(d, a, b0, b1) \
    asm volatile("mma.sync.aligned.m16n8k16.row.col.f32.f16.f16.f32 " \
                 "{%0,%1,%2,%3}, {%4,%5,%6,%7}, {%8,%9}, {%0,%1,%2,%3};" \
                 : "+f"((d)[0]), "+f"((d)[1]), "+f"((d)[2]), "+f"((d)[3]) \
                 : "r"((a)[0]), "r"((a)[1]), "r"((a)[2]), "r"((a)[3]), \
                   "r"(b0), "r"(b1))

// ======================= HMMA tile constants ================================
#define ROWB   144
#define TILE_B (128*ROWB)
#define OFF_A   0
#define OFF_B   (TILE_B)
#define STAGE_B (2*TILE_B)     // 36864 (A+B)
#define OFF_BL  (2*TILE_B)
#define STAGE3_B (3*TILE_B)    // 55296 (A + Bhi + Blo)
#define OFF_AL4 (TILE_B)
#define OFF_BH4 (2*TILE_B)
#define OFF_BL4 (3*TILE_B)
#define STAGE4_B (4*TILE_B)    // 73728 (Ah + Al + Bh + Bl)

// ======================= prep / conversion kernels ==========================
// one pass over x: xh[v][c] fp16 + xT[c][v] fp16 (32x32 tile transpose)
__global__ void k_prep_x(const float* __restrict__ x, __half* __restrict__ xh,
                         __half* __restrict__ xT)
{
    __shared__ __half t[32][33];
    const int v0 = blockIdx.x * 32, c0 = blockIdx.y * 32, b = blockIdx.z;
    const int tx = threadIdx.x, ty = threadIdx.y;   // 32 x 8
    #pragma unroll
    for (int j = 0; j < 4; j++) {
        int r = ty + j*8;
        __half h = __float2half(x[((long)b*VV + v0 + r)*CIN + c0 + tx]);
        xh[((long)b*VV + v0 + r)*CIN + c0 + tx] = h;
        t[r][tx] = h;
    }
    __syncthreads();
    #pragma unroll
    for (int j = 0; j < 4; j++) {
        int r = ty + j*8;
        xT[((long)b*CIN + c0 + r)*VV + v0 + tx] = t[tx][r];
    }
}

// phi16 [b][v][f] -> phiT [b][f][v]
__global__ void k_tr_phi(const __half* __restrict__ phi, __half* __restrict__ phiT)
{
    __shared__ __half t[32][33];
    const int v0 = blockIdx.x * 32, f0 = blockIdx.y * 32, b = blockIdx.z;
    const int tx = threadIdx.x, ty = threadIdx.y;
    #pragma unroll
    for (int j = 0; j < 4; j++) {
        int r = ty + j*8;
        t[r][tx] = phi[((long)b*VV + v0 + r)*FF + f0 + tx];
    }
    __syncthreads();
    #pragma unroll
    for (int j = 0; j < 4; j++) {
        int r = ty + j*8;
        phiT[((long)b*FF + f0 + r)*VV + v0 + tx] = t[tx][r];
    }
}

// HDT[b][e][v] = D[b][v] * H16[b][v][e]   (32x32 tile transpose + row scale)
__global__ void k_tr_hd(const __half* __restrict__ H, const float* __restrict__ D,
                        __half* __restrict__ HDT)
{
    __shared__ __half t[32][33];
    const int v0 = blockIdx.x * 32, e0 = blockIdx.y * 32, b = blockIdx.z;
    const int tx = threadIdx.x, ty = threadIdx.y;
    #pragma unroll
    for (int j = 0; j < 4; j++) {
        int r = ty + j*8;
        float d = D[b*VV + v0 + r];
        t[r][tx] = __float2half(d * __half2float(H[((long)b*VV + v0 + r)*EE + e0 + tx]));
    }
    __syncthreads();
    #pragma unroll
    for (int j = 0; j < 4; j++) {
        int r = ty + j*8;
        HDT[((long)b*EE + e0 + r)*VV + v0 + tx] = t[tx][r];
    }
}

// xT7[dxslot][b][c][u] = (uw+dx in [0,64)) ? xT[b][c][u+dx] : 0
__global__ void k_shift7(const __half* __restrict__ xT, __half* __restrict__ xT7)
{
    const int dxslot = blockIdx.y;
    const int dx = dxslot - 3;
    long base = (long)blockIdx.x * 2048 + threadIdx.x * 8;
    if (base >= (long)BB*CIN*VV) return;
    const int uw0 = (int)(base & 63);
    __half v[8];
    #pragma unroll
    for (int j = 0; j < 8; j++) {
        int uw = uw0 + j;
        v[j] = ((unsigned)(uw + dx) < 64u) ? xT[base + j + dx] : __half(0.f);
    }
    *(uint4*)(xT7 + (long)dxslot*BB*CIN*VV + base) = *(uint4*)v;
}

// wte[e][tap*256+c] = wm[tap][c][e] — 32x32 smem tile transpose (coalesced)
__global__ void k_cvt_wte(const float* __restrict__ wm, __half* __restrict__ wte)
{
    __shared__ __half t[32][33];
    const int k0 = blockIdx.x * 32, e0 = blockIdx.y * 32;   // k = tap*256+c
    const int tx = threadIdx.x, ty = threadIdx.y;
    #pragma unroll
    for (int j = 0; j < 4; j++) {
        int r = k0 + ty + j*8;                               // wm row (tap*CIN+c)
        t[ty + j*8][tx] = __float2half(wm[(long)r*EE + e0 + tx]);
    }
    __syncthreads();
    #pragma unroll
    for (int j = 0; j < 4; j++) {
        int r = ty + j*8;
        wte[(long)(e0 + r)*LD2 + k0 + tx] = t[tx][r];
    }
}

// merged small weight converts: wpht [f][c] and w2t hi/lo [o][c]
__global__ void k_cvt_small(const float* __restrict__ wph, __half* __restrict__ wpt,
                            const float* __restrict__ w2, __half* __restrict__ wh,
                            __half* __restrict__ wl)
{
    int i = blockIdx.x * 256 + threadIdx.x;
    if (i < FF*CIN) {
        int f = i / CIN, c = i % CIN;
        wpt[i] = __float2half(wph[c*FF + f]);
    }
    int j = i - FF*CIN;
    if (j >= 0 && j < COUT*CIN) {
        int o = j / CIN, c = j % CIN;
        float v = w2[c*COUT + o];
        __half h = __float2half(v);
        wh[j] = h;
        wl[j] = __float2half(v - __half2float(h));
    }
}

// P[b][f] = sum_v phiT[b][f][v]
__global__ void k_rowsum_phi(const __half* __restrict__ phiT, float* __restrict__ P)
{
    const int row  = blockIdx.x * 8 + (threadIdx.x >> 5);
    const int lane = threadIdx.x & 31;
    if (row >= BB*FF) return;
    const __half2* r = (const __half2*)(phiT + (long)row * VV);
    float s = 0.f;
    for (int c = lane; c < VV/2; c += 32) {
        float2 f = __half22float2(r[c]);
        s += f.x + f.y;
    }
    for (int o = 16; o; o >>= 1) s += __shfl_xor_sync(0xFFFFFFFFu, s, o);
    if (lane == 0) P[row] = s;
}

// at16[b][e][f] = half( a[b][f] * ( sum_s part[(b*14+s)][f][e] + P[b][f]*bm[e] ) )
__global__ void k_at_reduce(const float* __restrict__ part, const float* __restrict__ P,
                            const float* __restrict__ bm, const float* __restrict__ a,
                            __half* __restrict__ at)
{
    int i = blockIdx.x * 256 + threadIdx.x;
    if (i >= BB*EE*FF) return;
    int b = i / (EE*FF), r = i % (EE*FF);
    int e = r / FF, f = r % FF;
    float s = P[b*FF + f] * bm[e];
    #pragma unroll
    for (int sp = 0; sp < SPLITS2; sp++)
        s += part[((long)(b*SPLITS2 + sp))*FF*EE + f*EE + e];
    at[i] = __float2half(a[b*FF + f] * s);
}

// btmp hi/lo from tmp partials: v = Be[b][e] * sum_s part2[(b*8+s)][c][e]
__global__ void k_btmp_reduce(const float* __restrict__ part, const float* __restrict__ Be,
                              __half* __restrict__ bh, __half* __restrict__ bl)
{
    int i = blockIdx.x * 256 + threadIdx.x;     // b*CIN*EE + c*EE + e
    if (i >= BB*CIN*EE) return;
    int b = i / (CIN*EE), r = i % (CIN*EE);
    int e = r % EE;
    float s = 0.f;
    #pragma unroll
    for (int sp = 0; sp < SPLITK_P; sp++)
        s += part[((long)(b*SPLITK_P + sp))*CIN*EE + r];
    float v = Be[b*EE + e] * s;
    __half h = __float2half(v);
    bh[i] = h;
    bl[i] = __float2half(v - __half2float(h));
}

// ======================= HMMA generic NN GEMM (modes 0,1) ===================
template<int MODE>
__global__ __launch_bounds__(256, 2) void hgemm_nn(
    const __half* __restrict__ A, const __half* __restrict__ Bt, __half* __restrict__ C,
    const float* __restrict__ bias,
    int K, int N, int nk, long aB, long bB, long cB)
{
    extern __shared__ __align__(128) char smem[];
    const uint32_t sbase = smem_u32(smem);
    const int tid = threadIdx.x;
    const int wid = tid >> 5, lane = tid & 31;
    const int n0 = blockIdx.x * 128, m0 = blockIdx.y * 128, b = blockIdx.z;
    const int warpm = wid >> 1, warpn = wid & 1;

    const __half* Ab = A + (long)b * aB;
    const __half* Bb = Bt + (long)b * bB;

    const int rowA = tid >> 1, half = (tid & 1) * 32;
    const uint32_t dstRow = rowA * ROWB + half * 2;

    auto issue = [&](int it) {
        const int kc = it * 64;
        const long aoff = (long)(m0 + rowA) * K + kc + half;
        const long boff = (long)(n0 + rowA) * K + kc + half;
        const uint32_t stg = sbase + (it & 1) * STAGE_B;
        #pragma unroll
        for (int j = 0; j < 4; j++) {
            CP_ASYNC16(stg + OFF_A + dstRow + j*16, Ab + aoff + j*8, 16u);
            CP_ASYNC16(stg + OFF_B + dstRow + j*16, Bb + boff + j*8, 16u);
        }
        CP_COMMIT();
    };

    float acc[2][8][4];
    #pragma unroll
    for (int mt = 0; mt < 2; mt++)
        #pragma unroll
        for (int nt = 0; nt < 8; nt++)
            #pragma unroll
            for (int q = 0; q < 4; q++) acc[mt][nt][q] = 0.f;

    const uint32_t aLdOff = (warpm*32 + (lane & 15)) * ROWB + (lane >> 4) * 16;
    const uint32_t bLdOff = (warpn*64 + (lane & 7) + ((lane >> 4) & 1) * 8) * ROWB
                          + (((lane >> 3) & 1) * 8) * 2;

    issue(0);

    for (int it = 0; it < nk; it++) {
        if (it + 1 < nk) { issue(it + 1); CP_WAIT(1); }
        else             { CP_WAIT(0); }
        __syncthreads();

        const uint32_t stg = sbase + (it & 1) * STAGE_B;
        #pragma unroll
        for (int k16 = 0; k16 < 4; k16++) {
            const uint32_t kByte = k16 * 32;
            uint32_t ah[2][4];
            #pragma unroll
            for (int mt = 0; mt < 2; mt++)
                LDSM4(ah[mt], stg + OFF_A + aLdOff + mt * 16 * ROWB + kByte);
            #pragma unroll
            for (int np = 0; np < 4; np++) {
                uint32_t bb[4];
                LDSM4(bb, stg + OFF_B + bLdOff + np * 16 * ROWB + kByte);
                #pragma unroll
                for (int mt = 0; mt < 2; mt++) {
                    MMA16816H(acc[mt][2*np],   ah[mt], bb[0], bb[1]);
                    MMA16816H(acc[mt][2*np+1], ah[mt], bb[2], bb[3]);
                }
            }
        }
        __syncthreads();
    }

    const int r = lane >> 2, c2 = (lane & 3) * 2;
    #pragma unroll
    for (int mt = 0; mt < 2; mt++) {
        #pragma unroll
        for (int nt = 0; nt < 8; nt++) {
            const int m = m0 + warpm*32 + mt*16 + r;
            const int n = n0 + warpn*64 + nt*8 + c2;
            float c00 = acc[mt][nt][0], c01 = acc[mt][nt][1];
            float c10 = acc[mt][nt][2], c11 = acc[mt][nt][3];
            if (MODE == 0) {
                const float bx = bias[n], by = bias[n+1];
                c00 += bx; c01 += by; c10 += bx; c11 += by;
            } else {
                c00 = fabsf(c00); c01 = fabsf(c01);
                c10 = fabsf(c10); c11 = fabsf(c11);
            }
            __half* cp = C + (long)b*cB + (long)m * N + n;
            *(__half2*)cp          = __floats2half2_rn(c00, c01);
            *(__half2*)(cp + 8L*N) = __floats2half2_rn(c10, c11);
        }
    }
}

// ======================= G-GEMM: shifted correlations =======================
// blockIdx.y = z enumerated dx-major: tap = (z%7)*7 + z/7, so consecutive z
// share dx => the 7 dy-variants reuse the same 2MB xT7 slab in L2.
__global__ __launch_bounds__(256, 2) void gconv_mma(
    const __half* __restrict__ phiT, const __half* __restrict__ xT7,
    __half* __restrict__ G)
{
    extern __shared__ __align__(128) char smem[];
    const uint32_t sbase = smem_u32(smem);
    const int tid = threadIdx.x;
    const int wid = tid >> 5, lane = tid & 31;
    const int n0 = blockIdx.x * 128, z = blockIdx.y, b = blockIdx.z;
    const int tap = (z % 7) * 7 + (z / 7);     // dx-major enumeration
    const int dy = tap / 7 - 3, dx = tap % 7 - 3;
    const int warpm = wid >> 1, warpn = wid & 1;

    const __half* Ab = phiT + (long)b * FF * VV;
    const __half* Bb = xT7 + ((long)(dx + 3) * BB + b) * CIN * VV;

    const int rowA = tid >> 1, half = (tid & 1) * 32;
    const uint32_t dstRow = rowA * ROWB + half * 2;

    auto issue = [&](int it) {
        const long aoff = (long)rowA * VV + it * 64 + half;
        const int vh2 = it + dy;
        const bool ok = ((unsigned)vh2 < 64u);
        const uint32_t szB = ok ? 16u : 0u;
        const long boff = (long)(n0 + rowA) * VV + (ok ? vh2 : 0) * 64 + half;
        const uint32_t stg = sbase + (it & 1) * STAGE_B;
        #pragma unroll
        for (int j = 0; j < 4; j++) {
            CP_ASYNC16(stg + OFF_A + dstRow + j*16, Ab + aoff + j*8, 16u);
            CP_ASYNC16(stg + OFF_B + dstRow + j*16, Bb + boff + j*8, szB);
        }
        CP_COMMIT();
    };

    float acc[2][8][4];
    #pragma unroll
    for (int mt = 0; mt < 2; mt++)
        #pragma unroll
        for (int nt = 0; nt < 8; nt++)
            #pragma unroll
            for (int q = 0; q < 4; q++) acc[mt][nt][q] = 0.f;

    const uint32_t aLdOff = (warpm*32 + (lane & 15)) * ROWB + (lane >> 4) * 16;
    const uint32_t bLdOff = (warpn*64 + (lane & 7) + ((lane >> 4) & 1) * 8) * ROWB
                          + (((lane >> 3) & 1) * 8) * 2;

    issue(0);

    for (int it = 0; it < 64; it++) {
        if (it + 1 < 64) { issue(it + 1); CP_WAIT(1); }
        else             { CP_WAIT(0); }
        __syncthreads();

        // skip MMA when this chunk's B is entirely zfill (dy out of range)
        if ((unsigned)(it + dy) < 64u) {
            const uint32_t stg = sbase + (it & 1) * STAGE_B;
            #pragma unroll
            for (int k16 = 0; k16 < 4; k16++) {
                const uint32_t kByte = k16 * 32;
                uint32_t ah[2][4];
                #pragma unroll
                for (int mt = 0; mt < 2; mt++)
                    LDSM4(ah[mt], stg + OFF_A + aLdOff + mt * 16 * ROWB + kByte);
                #pragma unroll
                for (int np = 0; np < 4; np++) {
                    uint32_t bb[4];
                    LDSM4(bb, stg + OFF_B + bLdOff + np * 16 * ROWB + kByte);
                    #pragma unroll
                    for (int mt = 0; mt < 2; mt++) {
                        MMA16816H(acc[mt][2*np],   ah[mt], bb[0], bb[1]);
                        MMA16816H(acc[mt][2*np+1], ah[mt], bb[2], bb[3]);
                    }
                }
            }
        }
        __syncthreads();
    }

    const int r = lane >> 2, c2 = (lane & 3) * 2;
    __half* Gb = G + (long)b * FF * LD2 + tap * 256;
    #pragma unroll
    for (int mt = 0; mt < 2; mt++) {
        #pragma unroll
        for (int nt = 0; nt < 8; nt++) {
            const int m = warpm*32 + mt*16 + r;
            const int n = n0 + warpn*64 + nt*8 + c2;
            __half* cp = Gb + (long)m * LD2 + n;
            *(__half2*)cp            = __floats2half2_rn(acc[mt][nt][0], acc[mt][nt][1]);
            *(__half2*)(cp + 8L*LD2) = __floats2half2_rn(acc[mt][nt][2], acc[mt][nt][3]);
        }
    }
}

// ======================= stage-2: t partials (split-K) ======================
__global__ __launch_bounds__(256, 2) void hgemm_s2(
    const __half* __restrict__ G, const __half* __restrict__ wte,
    float* __restrict__ part)
{
    extern __shared__ __align__(128) char smem[];
    const uint32_t sbase = smem_u32(smem);
    const int tid = threadIdx.x;
    const int wid = tid >> 5, lane = tid & 31;
    const int n0 = blockIdx.x * 128, zb = blockIdx.z;
    const int b = zb / SPLITS2, s = zb % SPLITS2;
    const int kbeg = s * 14;
    const int warpm = wid >> 1, warpn = wid & 1;

    const __half* Ab = G + (long)b * FF * LD2;

    const int rowA = tid >> 1, half = (tid & 1) * 32;
    const uint32_t dstRow = rowA * ROWB + half * 2;

    auto issue = [&](int it) {
        const int kc = (kbeg + it) * 64;
        const long aoff = (long)rowA * LD2 + kc + half;
        const long boff = (long)(n0 + rowA) * LD2 + kc + half;
        const uint32_t stg = sbase + (it & 1) * STAGE_B;
        #pragma unroll
        for (int j = 0; j < 4; j++) {
            CP_ASYNC16(stg + OFF_A + dstRow + j*16, Ab + aoff + j*8, 16u);
            CP_ASYNC16(stg + OFF_B + dstRow + j*16, wte + boff + j*8, 16u);
        }
        CP_COMMIT();
    };

    float acc[2][8][4];
    #pragma unroll
    for (int mt = 0; mt < 2; mt++)
        #pragma unroll
        for (int nt = 0; nt < 8; nt++)
            #pragma unroll
            for (int q = 0; q < 4; q++) acc[mt][nt][q] = 0.f;

    const uint32_t aLdOff = (warpm*32 + (lane & 15)) * ROWB + (lane >> 4) * 16;
    const uint32_t bLdOff = (warpn*64 + (lane & 7) + ((lane >> 4) & 1) * 8) * ROWB
                          + (((lane >> 3) & 1) * 8) * 2;

    issue(0);

    for (int it = 0; it < 14; it++) {
        if (it + 1 < 14) { issue(it + 1); CP_WAIT(1); }
        else             { CP_WAIT(0); }
        __syncthreads();

        const uint32_t stg = sbase + (it & 1) * STAGE_B;
        #pragma unroll
        for (int k16 = 0; k16 < 4; k16++) {
            const uint32_t kByte = k16 * 32;
            uint32_t ah[2][4];
            #pragma unroll
            for (int mt = 0; mt < 2; mt++)
                LDSM4(ah[mt], stg + OFF_A + aLdOff + mt * 16 * ROWB + kByte);
            #pragma unroll
            for (int np = 0; np < 4; np++) {
                uint32_t bb[4];
                LDSM4(bb, stg + OFF_B + bLdOff + np * 16 * ROWB + kByte);
                #pragma unroll
                for (int mt = 0; mt < 2; mt++) {
                    MMA16816H(acc[mt][2*np],   ah[mt], bb[0], bb[1]);
                    MMA16816H(acc[mt][2*np+1], ah[mt], bb[2], bb[3]);
                }
            }
        }
        __syncthreads();
    }

    const int r = lane >> 2, c2 = (lane & 3) * 2;
    float* Cb = part + (long)zb * FF * EE;
    #pragma unroll
    for (int mt = 0; mt < 2; mt++) {
        #pragma unroll
        for (int nt = 0; nt < 8; nt++) {
            const int m = warpm*32 + mt*16 + r;
            const int n = n0 + warpn*64 + nt*8 + c2;
            float* cp = Cb + (long)m * EE + n;
            *(float2*)cp           = make_float2(acc[mt][nt][0], acc[mt][nt][1]);
            *(float2*)(cp + 8L*EE) = make_float2(acc[mt][nt][2], acc[mt][nt][3]);
        }
    }
}

// ======================= tmp GEMM: tmpT[c][e] split-K HMMA ==================
__global__ __launch_bounds__(256, 2) void hgemm_tmp(
    const __half* __restrict__ xT, const __half* __restrict__ HDT,
    float* __restrict__ part)
{
    extern __shared__ __align__(128) char smem[];
    const uint32_t sbase = smem_u32(smem);
    const int tid = threadIdx.x;
    const int wid = tid >> 5, lane = tid & 31;
    const int n0 = blockIdx.x * 128, m0 = blockIdx.y * 128, zb = blockIdx.z;
    const int b = zb / SPLITK_P, s = zb % SPLITK_P;
    const int kbeg = s * (64 / SPLITK_P);
    const int warpm = wid >> 1, warpn = wid & 1;

    const __half* Ab = xT + (long)b * CIN * VV;
    const __half* Bb = HDT + (long)b * EE * VV;

    const int rowA = tid >> 1, half = (tid & 1) * 32;
    const uint32_t dstRow = rowA * ROWB + half * 2;

    auto issue = [&](int it) {
        const int kc = (kbeg + it) * 64;
        const long aoff = (long)(m0 + rowA) * VV + kc + half;
        const long boff = (long)(n0 + rowA) * VV + kc + half;
        const uint32_t stg = sbase + (it & 1) * STAGE_B;
        #pragma unroll
        for (int j = 0; j < 4; j++) {
            CP_ASYNC16(stg + OFF_A + dstRow + j*16, Ab + aoff + j*8, 16u);
            CP_ASYNC16(stg + OFF_B + dstRow + j*16, Bb + boff + j*8, 16u);
        }
        CP_COMMIT();
    };

    float acc[2][8][4];
    #pragma unroll
    for (int mt = 0; mt < 2; mt++)
        #pragma unroll
        for (int nt = 0; nt < 8; nt++)
            #pragma unroll
            for (int q = 0; q < 4; q++) acc[mt][nt][q] = 0.f;

    const uint32_t aLdOff = (warpm*32 + (lane & 15)) * ROWB + (lane >> 4) * 16;
    const uint32_t bLdOff = (warpn*64 + (lane & 7) + ((lane >> 4) & 1) * 8) * ROWB
                          + (((lane >> 3) & 1) * 8) * 2;

    issue(0);

    const int nk = 64 / SPLITK_P;
    for (int it = 0; it < nk; it++) {
        if (it + 1 < nk) { issue(it + 1); CP_WAIT(1); }
        else             { CP_WAIT(0); }
        __syncthreads();

        const uint32_t stg = sbase + (it & 1) * STAGE_B;
        #pragma unroll
        for (int k16 = 0; k16 < 4; k16++) {
            const uint32_t kByte = k16 * 32;
            uint32_t ah[2][4];
            #pragma unroll
            for (int mt = 0; mt < 2; mt++)
                LDSM4(ah[mt], stg + OFF_A + aLdOff + mt * 16 * ROWB + kByte);
            #pragma unroll
            for (int np = 0; np < 4; np++) {
                uint32_t bb[4];
                LDSM4(bb, stg + OFF_B + bLdOff + np * 16 * ROWB + kByte);
                #pragma unroll
                for (int mt = 0; mt < 2; mt++) {
                    MMA16816H(acc[mt][2*np],   ah[mt], bb[0], bb[1]);
                    MMA16816H(acc[mt][2*np+1], ah[mt], bb[2], bb[3]);
                }
            }
        }
        __syncthreads();
    }

    const int r = lane >> 2, c2 = (lane & 3) * 2;
    float* Cb = part + (long)zb * CIN * EE;
    #pragma unroll
    for (int mt = 0; mt < 2; mt++) {
        #pragma unroll
        for (int nt = 0; nt < 8; nt++) {
            const int m = m0 + warpm*32 + mt*16 + r;
            const int n = n0 + warpn*64 + nt*8 + c2;
            float* cp = Cb + (long)m * EE + n;
            *(float2*)cp           = make_float2(acc[mt][nt][0], acc[mt][nt][1]);
            *(float2*)(cp + 8L*EE) = make_float2(acc[mt][nt][2], acc[mt][nt][3]);
        }
    }
}

// ======================= R-GEMM: 2-product, hi/lo fp16 out ==================
__global__ __launch_bounds__(256, 2) void hgemm_rgemm(
    const __half* __restrict__ H, const __half* __restrict__ BH,
    const __half* __restrict__ BL, const float* __restrict__ D,
    const float* __restrict__ x, __half* __restrict__ Rh, __half* __restrict__ Rl)
{
    extern __shared__ __align__(128) char smem[];
    const uint32_t sbase = smem_u32(smem);
    const int tid = threadIdx.x;
    const int wid = tid >> 5, lane = tid & 31;
    const int n0 = blockIdx.x * 128, m0 = blockIdx.y * 128, b = blockIdx.z;
    const int warpm = wid >> 1, warpn = wid & 1;

    const __half* Ab = H + (long)b * VV * EE;
    const __half* BHb = BH + (long)b * CIN * EE;
    const __half* BLb = BL + (long)b * CIN * EE;

    const int rowA = tid >> 1, half = (tid & 1) * 32;
    const uint32_t dstRow = rowA * ROWB + half * 2;

    auto issue = [&](int it) {
        const int kc = it * 64;
        const long aoff = (long)(m0 + rowA) * EE + kc + half;
        const long boff = (long)(n0 + rowA) * EE + kc + half;
        const uint32_t stg = sbase + (it & 1) * STAGE3_B;
        #pragma unroll
        for (int j = 0; j < 4; j++) {
            CP_ASYNC16(stg + OFF_A  + dstRow + j*16, Ab  + aoff + j*8, 16u);
            CP_ASYNC16(stg + OFF_B  + dstRow + j*16, BHb + boff + j*8, 16u);
            CP_ASYNC16(stg + OFF_BL + dstRow + j*16, BLb + boff + j*8, 16u);
        }
        CP_COMMIT();
    };

    float acc[2][8][4];
    #pragma unroll
    for (int mt = 0; mt < 2; mt++)
        #pragma unroll
        for (int nt = 0; nt < 8; nt++)
            #pragma unroll
            for (int q = 0; q < 4; q++) acc[mt][nt][q] = 0.f;

    const uint32_t aLdOff = (warpm*32 + (lane & 15)) * ROWB + (lane >> 4) * 16;
    const uint32_t bLdOff = (warpn*64 + (lane & 7) + ((lane >> 4) & 1) * 8) * ROWB
                          + (((lane >> 3) & 1) * 8) * 2;

    issue(0);

    for (int it = 0; it < 4; it++) {
        if (it + 1 < 4) { issue(it + 1); CP_WAIT(1); }
        else            { CP_WAIT(0); }
        __syncthreads();

        const uint32_t stg = sbase + (it & 1) * STAGE3_B;
        #pragma unroll
        for (int k16 = 0; k16 < 4; k16++) {
            const uint32_t kByte = k16 * 32;
            uint32_t ah[2][4];
            #pragma unroll
            for (int mt = 0; mt < 2; mt++)
                LDSM4(ah[mt], stg + OFF_A + aLdOff + mt * 16 * ROWB + kByte);
            #pragma unroll
            for (int np = 0; np < 4; np++) {
                uint32_t bh[4], bl[4];
                LDSM4(bh, stg + OFF_B  + bLdOff + np * 16 * ROWB + kByte);
                LDSM4(bl, stg + OFF_BL + bLdOff + np * 16 * ROWB + kByte);
                #pragma unroll
                for (int mt = 0; mt < 2; mt++) {
                    MMA16816H(acc[mt][2*np],   ah[mt], bh[0], bh[1]);
                    MMA16816H(acc[mt][2*np+1], ah[mt], bh[2], bh[3]);
                    MMA16816H(acc[mt][2*np],   ah[mt], bl[0], bl[1]);
                    MMA16816H(acc[mt][2*np+1], ah[mt], bl[2], bl[3]);
                }
            }
        }
        __syncthreads();
    }

    const int r = lane >> 2, c2 = (lane & 3) * 2;
    #pragma unroll
    for (int mt = 0; mt < 2; mt++) {
        #pragma unroll
        for (int nt = 0; nt < 8; nt++) {
            const int m = m0 + warpm*32 + mt*16 + r;
            const int n = n0 + warpn*64 + nt*8 + c2;
            const float d0 = D[b*VV + m], d1 = D[b*VV + m + 8];
            const float* xp0 = x + (long)b*VV*CIN + (long)m * CIN + n;
            float2 x0 = *(const float2*)xp0;
            float2 x1 = *(const float2*)(xp0 + 8L*CIN);
            float v00 = x0.x - d0*acc[mt][nt][0], v01 = x0.y - d0*acc[mt][nt][1];
            float v10 = x1.x - d1*acc[mt][nt][2], v11 = x1.y - d1*acc[mt][nt][3];
            long off = (long)b*VV*CIN + (long)m * CIN + n;
            __half2 h2a = __floats2half2_rn(v00, v01);
            __half2 h2b = __floats2half2_rn(v10, v11);
            *(__half2*)&Rh[off]          = h2a;
            *(__half2*)&Rh[off + 8L*CIN] = h2b;
            float2 fa = __half22float2(h2a);
            float2 fb = __half22float2(h2b);
            *(__half2*)&Rl[off]          = __floats2half2_rn(v00 - fa.x, v01 - fa.y);
            *(__half2*)&Rl[off + 8L*CIN] = __floats2half2_rn(v10 - fb.x, v11 - fb.y);
        }
    }
}

// ======================= out-GEMM: 3-product HMMA, fp32 out =================
__global__ __launch_bounds__(256) void hgemm_out3(
    const __half* __restrict__ Rh, const __half* __restrict__ Rl,
    const __half* __restrict__ W2h, const __half* __restrict__ W2l,
    const float* __restrict__ bias, float* __restrict__ out)
{
    extern __shared__ __align__(128) char smem[];
    const uint32_t sbase = smem_u32(smem);
    const int tid = threadIdx.x;
    const int wid = tid >> 5, lane = tid & 31;
    const int n0 = blockIdx.x * 128, m0 = blockIdx.y * 128;
    const int warpm = wid >> 1, warpn = wid & 1;

    const int rowA = tid >> 1, half = (tid & 1) * 32;
    const uint32_t dstRow = rowA * ROWB + half * 2;

    auto issue = [&](int it) {
        const int kc = it * 64;
        const long aoff = (long)(m0 + rowA) * CIN + kc + half;
        const long boff = (long)(n0 + rowA) * CIN + kc + half;
        const uint32_t stg = sbase + (it & 1) * STAGE4_B;
        #pragma unroll
        for (int j = 0; j < 4; j++) {
            CP_ASYNC16(stg + OFF_A   + dstRow + j*16, Rh  + aoff + j*8, 16u);
            CP_ASYNC16(stg + OFF_AL4 + dstRow + j*16, Rl  + aoff + j*8, 16u);
            CP_ASYNC16(stg + OFF_BH4 + dstRow + j*16, W2h + boff + j*8, 16u);
            CP_ASYNC16(stg + OFF_BL4 + dstRow + j*16, W2l + boff + j*8, 16u);
        }
        CP_COMMIT();
    };

    float acc[2][8][4];
    #pragma unroll
    for (int mt = 0; mt < 2; mt++)
        #pragma unroll
        for (int nt = 0; nt < 8; nt++)
            #pragma unroll
            for (int q = 0; q < 4; q++) acc[mt][nt][q] = 0.f;

    const uint32_t aLdOff = (warpm*32 + (lane & 15)) * ROWB + (lane >> 4) * 16;
    const uint32_t bLdOff = (warpn*64 + (lane & 7) + ((lane >> 4) & 1) * 8) * ROWB
                          + (((lane >> 3) & 1) * 8) * 2;

    issue(0);

    for (int it = 0; it < 4; it++) {
        if (it + 1 < 4) { issue(it + 1); CP_WAIT(1); }
        else            { CP_WAIT(0); }
        __syncthreads();

        const uint32_t stg = sbase + (it & 1) * STAGE4_B;
        #pragma unroll
        for (int k16 = 0; k16 < 4; k16++) {
            const uint32_t kByte = k16 * 32;
            uint32_t ah[2][4], al[2][4];
            #pragma unroll
            for (int mt = 0; mt < 2; mt++) {
                LDSM4(ah[mt], stg + OFF_A   + aLdOff + mt * 16 * ROWB + kByte);
                LDSM4(al[mt], stg + OFF_AL4 + aLdOff + mt * 16 * ROWB + kByte);
            }
            #pragma unroll
            for (int np = 0; np < 4; np++) {
                uint32_t bh[4], bl[4];
                LDSM4(bh, stg + OFF_BH4 + bLdOff + np * 16 * ROWB + kByte);
                LDSM4(bl, stg + OFF_BL4 + bLdOff + np * 16 * ROWB + kByte);
                #pragma unroll
                for (int mt = 0; mt < 2; mt++) {
                    MMA16816H(acc[mt][2*np],   ah[mt], bh[0], bh[1]);
                    MMA16816H(acc[mt][2*np+1], ah[mt], bh[2], bh[3]);
                    MMA16816H(acc[mt][2*np],   ah[mt], bl[0], bl[1]);
                    MMA16816H(acc[mt][2*np+1], ah[mt], bl[2], bl[3]);
                    MMA16816H(acc[mt][2*np],   al[mt], bh[0], bh[1]);
                    MMA16816H(acc[mt][2*np+1], al[mt], bh[2], bh[3]);
                }
            }
        }
        __syncthreads();
    }

    const int r = lane >> 2, c2 = (lane & 3) * 2;
    #pragma unroll
    for (int mt = 0; mt < 2; mt++) {
        #pragma unroll
        for (int nt = 0; nt < 8; nt++) {
            const int m = m0 + warpm*32 + mt*16 + r;
            const int n = n0 + warpn*64 + nt*8 + c2;
            const float bx = bias[n], by = bias[n+1];
            float* cp = out + (long)m * COUT + n;
            *(float2*)cp             = make_float2(acc[mt][nt][0] + bx, acc[mt][nt][1] + by);
            *(float2*)(cp + 8L*COUT) = make_float2(acc[mt][nt][2] + bx, acc[mt][nt][3] + by);
        }
    }
}

// -------------------- small reduction / pointwise kernels -------------------
__global__ void k_xpart(const float* __restrict__ x, float* __restrict__ P)
{
    const int b = blockIdx.x, p = blockIdx.y, c = threadIdx.x;
    const float* base = x + ((long)b * VV + p * 128) * CIN + c;
    float s = 0.f;
    for (int v = 0; v < 128; v++) s += base[(long)v * CIN];
    P[(b * 32 + p) * CIN + c] = s;
}

__global__ void k_xmean(const float* __restrict__ P, float* __restrict__ xm)
{
    const int b = blockIdx.x, c = threadIdx.x;
    float s = 0.f;
    for (int p = 0; p < 32; p++) s += P[(b * 32 + p) * CIN + c];
    xm[b * CIN + c] = s * (1.0f / VV);
}

__global__ void k_a(const float* __restrict__ xmg, const float* __restrict__ wa,
                    const float* __restrict__ ba, float* __restrict__ a)
{
    __shared__ float xm[CIN];
    const int b = blockIdx.x, f = threadIdx.x;
    xm[f] = xmg[b * CIN + f];
    xm[f + 128] = xmg[b * CIN + f + 128];
    __syncthreads();
    float s = ba[f];
    #pragma unroll 8
    for (int c = 0; c < CIN; c++) s += xm[c] * wa[c * FF + f];
    a[b * FF + f] = s;
}

__global__ void k_degD(const __half* __restrict__ H, float* __restrict__ D)
{
    const int row  = blockIdx.x * 8 + (threadIdx.x >> 5);
    const int lane = threadIdx.x & 31;
    if (row >= BB * VV) return;
    const __half2* r = (const __half2*)(H + (long)row * EE);
    float s = 0.f;
    for (int c = lane; c < EE/2; c += 32) {
        float2 f = __half22float2(r[c]);
        s += f.x + f.y;
    }
    for (int o = 16; o; o >>= 1) s += __shfl_xor_sync(0xFFFFFFFFu, s, o);
    if (lane == 0) D[row] = rsqrtf(s);
}

__global__ void k_bpart(const __half* __restrict__ H, float* __restrict__ P)
{
    const int b = blockIdx.x, p = blockIdx.y, e = threadIdx.x;
    const __half* base = H + ((long)b * VV + p * 256) * EE + e;
    float s = 0.f;
    for (int v = 0; v < 256; v++) s += __half2float(base[(long)v * EE]);
    P[(b * 16 + p) * EE + e] = s;
}

__global__ void k_finishBe(const float* __restrict__ P, float* __restrict__ Be)
{
    const int b = blockIdx.x, e = threadIdx.x;
    float s = 0.f;
    for (int p = 0; p < 16; p++) s += P[(b * 16 + p) * EE + e];
    Be[b * EE + e] = 1.0f / s;
}

// ---------------------------------------------------------------------------
extern "C" void kernel_launch(void* const* d_in, const int* in_sizes, int n_in,
                              void* d_out, int out_size)
{
    const float* x   = (const float*)d_in[0];
    const float* wph = (const float*)d_in[1];
    const float* bph = (const float*)d_in[2];
    const float* wa  = (const float*)d_in[3];
    const float* ba  = (const float*)d_in[4];
    const float* wm  = (const float*)d_in[5];
    const float* bm  = (const float*)d_in[6];
    const float* w2  = (const float*)d_in[7];
    const float* b2  = (const float*)d_in[8];
    float* out = (float*)d_out;

    float *Db, *Beb, *ab, *Pb, *xp, *xmg, *bp, *p1, *p2;
    __half *xh, *xT, *xT7, *phi16, *phiT, *H16, *HDT, *Rh, *Rl;
    __half *G, *wte, *wpht, *at16, *btH, *btL, *w2th, *w2tl;
    cudaGetSymbolAddress((void**)&phi16, g_phi16);
    cudaGetSymbolAddress((void**)&phiT, g_phiT);
    cudaGetSymbolAddress((void**)&H16,  g_H16);
    cudaGetSymbolAddress((void**)&HDT,  g_HDT);
    cudaGetSymbolAddress((void**)&Rh,   g_Rh);
    cudaGetSymbolAddress((void**)&Rl,   g_Rl);
    cudaGetSymbolAddress((void**)&Db,   g_D);
    cudaGetSymbolAddress((void**)&Beb,  g_Be);
    cudaGetSymbolAddress((void**)&ab,   g_a);
    cudaGetSymbolAddress((void**)&Pb,   g_P);
    cudaGetSymbolAddress((void**)&xp,   g_xpart);
    cudaGetSymbolAddress((void**)&xmg,  g_xmean);
    cudaGetSymbolAddress((void**)&bp,   g_bpart);
    cudaGetSymbolAddress((void**)&p1,   g_part1);
    cudaGetSymbolAddress((void**)&p2,   g_part2);
    cudaGetSymbolAddress((void**)&xh,   g_xh);
    cudaGetSymbolAddress((void**)&xT,   g_xT);
    cudaGetSymbolAddress((void**)&xT7,  g_xT7);
    cudaGetSymbolAddress((void**)&G,    g_G);
    cudaGetSymbolAddress((void**)&wte,  g_wte);
    cudaGetSymbolAddress((void**)&wpht, g_wpht);
    cudaGetSymbolAddress((void**)&at16, g_at);
    cudaGetSymbolAddress((void**)&btH,  g_btmpH);
    cudaGetSymbolAddress((void**)&btL,  g_btmpL);
    cudaGetSymbolAddress((void**)&w2th, g_w2th);
    cudaGetSymbolAddress((void**)&w2tl, g_w2tl);

    cudaFuncSetAttribute(hgemm_nn<0>, cudaFuncAttributeMaxDynamicSharedMemorySize, STAGE_B*2);
    cudaFuncSetAttribute(hgemm_nn<1>, cudaFuncAttributeMaxDynamicSharedMemorySize, STAGE_B*2);
    cudaFuncSetAttribute(gconv_mma,   cudaFuncAttributeMaxDynamicSharedMemorySize, STAGE_B*2);
    cudaFuncSetAttribute(hgemm_s2,    cudaFuncAttributeMaxDynamicSharedMemorySize, STAGE_B*2);
    cudaFuncSetAttribute(hgemm_tmp,   cudaFuncAttributeMaxDynamicSharedMemorySize, STAGE_B*2);
    cudaFuncSetAttribute(hgemm_rgemm, cudaFuncAttributeMaxDynamicSharedMemorySize, STAGE3_B*2);
    cudaFuncSetAttribute(hgemm_out3,  cudaFuncAttributeMaxDynamicSharedMemorySize, STAGE4_B*2);

    // 0) conversions / transposes / shifted copies
    k_prep_x<<<dim3(VV/32, CIN/32, BB), dim3(32, 8)>>>(x, xh, xT);
    k_shift7<<<dim3((unsigned)(((long)BB*VV*CIN + 2047)/2048), 7), 256>>>(xT, xT7);
    k_cvt_wte<<<dim3(LD2/32, EE/32), dim3(32, 8)>>>(wm, wte);
    k_cvt_small<<<((FF + COUT)*CIN + 255)/256, 256>>>(wph, wpht, w2, w2th, w2tl);

    // 1) pooled mean + a vector
    k_xpart<<<dim3(BB, 32), 256>>>(x, xp);
    k_xmean<<<BB, 256>>>(xp, xmg);
    k_a<<<BB, 128>>>(xmg, wa, ba, ab);

    // 2) phi = x @ w_phi + b_phi  (HMMA), then transpose + column sums
    hgemm_nn<0><<<dim3(1, 256, 1), 256, STAGE_B*2>>>(
        xh, wpht, phi16, bph, CIN, FF, 4, 0, 0, 0);
    k_tr_phi<<<dim3(VV/32, FF/32, BB), dim3(32, 8)>>>(phi16, phiT);
    k_rowsum_phi<<<BB*FF/8, 256>>>(phiT, Pb);

    // 3) G = 49 shifted correlations phi^T (x) x  (dx-major CTA order)
    gconv_mma<<<dim3(CIN/128, 49, BB), 256, STAGE_B*2>>>(phiT, xT7, G);

    // 4) t = G @ w (+ rank-1 bias), split-K, fold a -> at16
    hgemm_s2<<<dim3(EE/128, 1, BB*SPLITS2), 256, STAGE_B*2>>>(G, wte, p1);
    k_at_reduce<<<(BB*EE*FF + 255)/256, 256>>>(p1, Pb, bm, ab, at16);

    // 5) H = | phi @ (diag(a) t) |
    hgemm_nn<1><<<dim3(2, 32, BB), 256, STAGE_B*2>>>(
        phi16, at16, H16, nullptr, FF, EE, 2,
        (long)VV*FF, (long)EE*FF, (long)VV*EE);

    // 6) degrees + HDT
    k_degD<<<(BB*VV)/8, 256>>>(H16, Db);
    k_bpart<<<dim3(BB, 16), 256>>>(H16, bp);
    k_finishBe<<<BB, 256>>>(bp, Beb);
    k_tr_hd<<<dim3(VV/32, EE/32, BB), dim3(32, 8)>>>(H16, Db, HDT);

    // 7) tmpT = xT @ HDT^T  (split-K HMMA), reduce + Binv fold -> btmp hi/lo
    hgemm_tmp<<<dim3(EE/128, CIN/128, BB*SPLITK_P), 256, STAGE_B*2>>>(xT, HDT, p2);
    k_btmp_reduce<<<(BB*CIN*EE + 255)/256, 256>>>(p2, Beb, btH, btL);

    // 8) R = x - D^-1/2 * (H @ (btmpH+btmpL)^T)   -> Rh/Rl fp16 pair
    hgemm_rgemm<<<dim3(2, 32, BB), 256, STAGE3_B*2>>>(H16, btH, btL, Db, x, Rh, Rl);

    // 9) out = (Rh+Rl) @ (w2h+w2l) + b2   (3-product HMMA, fp32 out)
    hgemm_out3<<<dim3(COUT/128, (BB*VV)/128, 1), 256, STAGE4_B*2>>>(
        Rh, Rl, w2th, w2tl, b2, out);
}